// round 2
// baseline (speedup 1.0000x reference)
#include <cuda_runtime.h>
#include <cuda_bf16.h>

// LinearNavigator fused: preproc -> LSTM(2->20) -> LSTM(20->20) -> head -> x[1..5]
// B = 1048576, H = 20. 2 elements per thread, fp32x2 packed math (FFMA2).
// Output: out[B,5], h_stack[2,B,20], c_stack[2,B,20]

#define NB 1048576
#define HDIM 20

typedef unsigned long long u64;

__device__ __forceinline__ u64 fma2(u64 a, u64 b, u64 c) {
    u64 d; asm("fma.rn.f32x2 %0, %1, %2, %3;" : "=l"(d) : "l"(a), "l"(b), "l"(c)); return d;
}
__device__ __forceinline__ u64 pack2(float lo, float hi) {
    u64 r; asm("mov.b64 %0, {%1, %2};" : "=l"(r) : "f"(lo), "f"(hi)); return r;
}
__device__ __forceinline__ float2 unpack2(u64 v) {
    float2 r; asm("mov.b64 {%0, %1}, %2;" : "=f"(r.x), "=f"(r.y) : "l"(v)); return r;
}

__device__ __forceinline__ float sigmoid_(float x) {
    return __fdividef(1.0f, 1.0f + __expf(-x));
}
__device__ __forceinline__ float tanh_(float x) {
    float e = __expf(2.0f * x);
    return 1.0f - __fdividef(2.0f, e + 1.0f);
}

__global__ __launch_bounds__(128)
void navi_kernel(const float* __restrict__ inp,
                 const float* __restrict__ hidden,
                 const float* __restrict__ cell,
                 const float* __restrict__ W_ih1, const float* __restrict__ W_hh1,
                 const float* __restrict__ b_ih1, const float* __restrict__ b_hh1,
                 const float* __restrict__ W_ih2, const float* __restrict__ W_hh2,
                 const float* __restrict__ b_ih2, const float* __restrict__ b_hh2,
                 const float* __restrict__ W_out, const float* __restrict__ b_out,
                 float* __restrict__ out)
{
    // Weights duplicated pairwise: quad (w0,w0,w1,w1) -> one LDS.128 yields two
    // splatted f32x2 operands for FFMA2.
    __shared__ ulonglong2 sWih1q[80];        // (80,2)  -> [r] = (w0,w0,w1,w1)
    __shared__ ulonglong2 sWhh1q[80 * 10];   // (80,20) -> [r*10+p]
    __shared__ ulonglong2 sWih2q[80 * 10];
    __shared__ ulonglong2 sWhh2q[80 * 10];
    __shared__ u64 sb1d[80];
    __shared__ u64 sb2d[80];
    __shared__ u64 sWod[HDIM];
    __shared__ float sbo;

    const int t = threadIdx.x;
    {
        float* f = (float*)sWih1q;
        for (int i = t; i < 320; i += 128) {
            int r = i >> 2, c = i & 3;
            f[i] = W_ih1[r * 2 + (c >> 1)];
        }
        f = (float*)sWhh1q;
        for (int i = t; i < 3200; i += 128) {
            int r = i / 40, c = i % 40;
            f[i] = W_hh1[r * 20 + (c >> 2) * 2 + ((c >> 1) & 1)];
        }
        f = (float*)sWih2q;
        for (int i = t; i < 3200; i += 128) {
            int r = i / 40, c = i % 40;
            f[i] = W_ih2[r * 20 + (c >> 2) * 2 + ((c >> 1) & 1)];
        }
        f = (float*)sWhh2q;
        for (int i = t; i < 3200; i += 128) {
            int r = i / 40, c = i % 40;
            f[i] = W_hh2[r * 20 + (c >> 2) * 2 + ((c >> 1) & 1)];
        }
        for (int j = t; j < 80; j += 128) {
            float b1 = b_ih1[j] + b_hh1[j];
            sb1d[j] = pack2(b1, b1);
            float b2 = b_ih2[j] + b_hh2[j];
            sb2d[j] = pack2(b2, b2);
        }
        for (int j = t; j < HDIM; j += 128) {
            float w = W_out[j];
            sWod[j] = pack2(w, w);
        }
        if (t == 0) sbo = b_out[0];
    }
    __syncthreads();

    const size_t b0 = ((size_t)blockIdx.x * blockDim.x + t) * 2;

    // ---------------- preproc (scalar per element, then pack) ----------------
    const float THR = 4.5399929762484854e-05f;  // exp(-10)
    const float E10 = 22026.465794806718f;      // exp(10)
    float v0 = inp[b0], v1 = inp[b0 + 1];
    float x0a, x1a, x0b, x1b;
    {
        float av = fabsf(v0);
        if (av >= THR) { x0a = __logf(av + 1e-8f) * 0.1f; x1a = (v0 > 0.0f) ? 1.0f : -1.0f; }
        else           { x0a = -1.0f; x1a = E10 * v0; }
        av = fabsf(v1);
        if (av >= THR) { x0b = __logf(av + 1e-8f) * 0.1f; x1b = (v1 > 0.0f) ? 1.0f : -1.0f; }
        else           { x0b = -1.0f; x1b = E10 * v1; }
    }
    const u64 x0p = pack2(x0a, x0b);
    const u64 x1p = pack2(x1a, x1b);

    // ---------------- load layer-1 state, packed ----------------
    u64 h0p[HDIM], c0p[HDIM];
    {
        const float4* hp = reinterpret_cast<const float4*>(hidden + b0 * HDIM);
        const float4* cp = reinterpret_cast<const float4*>(cell   + b0 * HDIM);
        #pragma unroll
        for (int q = 0; q < 5; q++) {
            float4 a = hp[q], b = hp[q + 5];
            h0p[4*q+0] = pack2(a.x, b.x); h0p[4*q+1] = pack2(a.y, b.y);
            h0p[4*q+2] = pack2(a.z, b.z); h0p[4*q+3] = pack2(a.w, b.w);
            a = cp[q]; b = cp[q + 5];
            c0p[4*q+0] = pack2(a.x, b.x); c0p[4*q+1] = pack2(a.y, b.y);
            c0p[4*q+2] = pack2(a.z, b.z); c0p[4*q+3] = pack2(a.w, b.w);
        }
    }

    // ---------------- LSTM layer 1 ----------------
    u64 hn1p[HDIM];
    #pragma unroll 1
    for (int j = 0; j < HDIM; j++) {
        u64 gi = sb1d[j], gf = sb1d[j + 20], gg = sb1d[j + 40], go = sb1d[j + 60];
        ulonglong2 w;
        w = sWih1q[j];      gi = fma2(x0p, w.x, gi); gi = fma2(x1p, w.y, gi);
        w = sWih1q[j + 20]; gf = fma2(x0p, w.x, gf); gf = fma2(x1p, w.y, gf);
        w = sWih1q[j + 40]; gg = fma2(x0p, w.x, gg); gg = fma2(x1p, w.y, gg);
        w = sWih1q[j + 60]; go = fma2(x0p, w.x, go); go = fma2(x1p, w.y, go);
        const ulonglong2* wri = &sWhh1q[j * 10];
        const ulonglong2* wrf = &sWhh1q[(j + 20) * 10];
        const ulonglong2* wrg = &sWhh1q[(j + 40) * 10];
        const ulonglong2* wro = &sWhh1q[(j + 60) * 10];
        #pragma unroll
        for (int p = 0; p < 10; p++) {
            const u64 ha = h0p[2*p], hb = h0p[2*p+1];
            w = wri[p]; gi = fma2(ha, w.x, gi); gi = fma2(hb, w.y, gi);
            w = wrf[p]; gf = fma2(ha, w.x, gf); gf = fma2(hb, w.y, gf);
            w = wrg[p]; gg = fma2(ha, w.x, gg); gg = fma2(hb, w.y, gg);
            w = wro[p]; go = fma2(ha, w.x, go); go = fma2(hb, w.y, go);
        }
        float2 fi = unpack2(gi), ff = unpack2(gf), fg = unpack2(gg), fo = unpack2(go);
        float2 fc = unpack2(c0p[j]);
        float cl = sigmoid_(ff.x) * fc.x + sigmoid_(fi.x) * tanh_(fg.x);
        float ch = sigmoid_(ff.y) * fc.y + sigmoid_(fi.y) * tanh_(fg.y);
        float hl = sigmoid_(fo.x) * tanh_(cl);
        float hh = sigmoid_(fo.y) * tanh_(ch);
        c0p[j]  = pack2(cl, ch);
        hn1p[j] = pack2(hl, hh);
    }

    // store layer-1 outputs (h_stack[0], c_stack[0]) vectorized
    {
        float4* hp = reinterpret_cast<float4*>(out + (size_t)5 * NB + b0 * HDIM);
        float4* cp = reinterpret_cast<float4*>(out + (size_t)5 * NB + (size_t)2 * NB * HDIM + b0 * HDIM);
        #pragma unroll
        for (int q = 0; q < 5; q++) {
            float2 a0 = unpack2(hn1p[4*q+0]), a1 = unpack2(hn1p[4*q+1]);
            float2 a2 = unpack2(hn1p[4*q+2]), a3 = unpack2(hn1p[4*q+3]);
            hp[q]     = make_float4(a0.x, a1.x, a2.x, a3.x);
            hp[q + 5] = make_float4(a0.y, a1.y, a2.y, a3.y);
            a0 = unpack2(c0p[4*q+0]); a1 = unpack2(c0p[4*q+1]);
            a2 = unpack2(c0p[4*q+2]); a3 = unpack2(c0p[4*q+3]);
            cp[q]     = make_float4(a0.x, a1.x, a2.x, a3.x);
            cp[q + 5] = make_float4(a0.y, a1.y, a2.y, a3.y);
        }
    }

    // ---------------- load layer-2 state, packed (reuse c0p/h0p registers) ----------------
    u64 h1p[HDIM], c1p[HDIM];
    {
        const float4* hp = reinterpret_cast<const float4*>(hidden + (size_t)NB * HDIM + b0 * HDIM);
        const float4* cp = reinterpret_cast<const float4*>(cell   + (size_t)NB * HDIM + b0 * HDIM);
        #pragma unroll
        for (int q = 0; q < 5; q++) {
            float4 a = hp[q], b = hp[q + 5];
            h1p[4*q+0] = pack2(a.x, b.x); h1p[4*q+1] = pack2(a.y, b.y);
            h1p[4*q+2] = pack2(a.z, b.z); h1p[4*q+3] = pack2(a.w, b.w);
            a = cp[q]; b = cp[q + 5];
            c1p[4*q+0] = pack2(a.x, b.x); c1p[4*q+1] = pack2(a.y, b.y);
            c1p[4*q+2] = pack2(a.z, b.z); c1p[4*q+3] = pack2(a.w, b.w);
        }
    }

    // ---------------- LSTM layer 2 + head (h/c stored per-j to cap registers) ----
    float* hb1 = out + (size_t)5 * NB + (size_t)NB * HDIM;
    float* cb1 = out + (size_t)5 * NB + (size_t)3 * NB * HDIM;
    u64 op = pack2(sbo, sbo);
    #pragma unroll 1
    for (int j = 0; j < HDIM; j++) {
        u64 gi = sb2d[j], gf = sb2d[j + 20], gg = sb2d[j + 40], go = sb2d[j + 60];
        const ulonglong2* wii = &sWih2q[j * 10];
        const ulonglong2* wif = &sWih2q[(j + 20) * 10];
        const ulonglong2* wig = &sWih2q[(j + 40) * 10];
        const ulonglong2* wio = &sWih2q[(j + 60) * 10];
        const ulonglong2* wri = &sWhh2q[j * 10];
        const ulonglong2* wrf = &sWhh2q[(j + 20) * 10];
        const ulonglong2* wrg = &sWhh2q[(j + 40) * 10];
        const ulonglong2* wro = &sWhh2q[(j + 60) * 10];
        ulonglong2 w;
        #pragma unroll
        for (int p = 0; p < 10; p++) {
            const u64 xa = hn1p[2*p], xb = hn1p[2*p+1];
            const u64 ha = h1p[2*p],  hb = h1p[2*p+1];
            w = wii[p]; gi = fma2(xa, w.x, gi); gi = fma2(xb, w.y, gi);
            w = wri[p]; gi = fma2(ha, w.x, gi); gi = fma2(hb, w.y, gi);
            w = wif[p]; gf = fma2(xa, w.x, gf); gf = fma2(xb, w.y, gf);
            w = wrf[p]; gf = fma2(ha, w.x, gf); gf = fma2(hb, w.y, gf);
            w = wig[p]; gg = fma2(xa, w.x, gg); gg = fma2(xb, w.y, gg);
            w = wrg[p]; gg = fma2(ha, w.x, gg); gg = fma2(hb, w.y, gg);
            w = wio[p]; go = fma2(xa, w.x, go); go = fma2(xb, w.y, go);
            w = wro[p]; go = fma2(ha, w.x, go); go = fma2(hb, w.y, go);
        }
        float2 fi = unpack2(gi), ff = unpack2(gf), fg = unpack2(gg), fo = unpack2(go);
        float2 fc = unpack2(c1p[j]);
        float cl = sigmoid_(ff.x) * fc.x + sigmoid_(fi.x) * tanh_(fg.x);
        float ch = sigmoid_(ff.y) * fc.y + sigmoid_(fi.y) * tanh_(fg.y);
        float hl = sigmoid_(fo.x) * tanh_(cl);
        float hh = sigmoid_(fo.y) * tanh_(ch);
        const size_t base = b0 * HDIM + j;
        cb1[base] = cl;  cb1[base + HDIM] = ch;
        hb1[base] = hl;  hb1[base + HDIM] = hh;
        op = fma2(pack2(hl, hh), sWod[j], op);
    }

    // ---------------- head: out[B,5] ----------------
    float2 oo = unpack2(op);
    float* o5 = out + b0 * 5;
    #pragma unroll
    for (int s = 0; s < 5; s++) {
        o5[s]     = oo.x * (float)(s + 1);
        o5[s + 5] = oo.y * (float)(s + 1);
    }
}

extern "C" void kernel_launch(void* const* d_in, const int* in_sizes, int n_in,
                              void* d_out, int out_size) {
    const float* inp    = (const float*)d_in[0];
    const float* hidden = (const float*)d_in[1];
    const float* cell   = (const float*)d_in[2];
    const float* W_ih1  = (const float*)d_in[3];
    const float* W_hh1  = (const float*)d_in[4];
    const float* b_ih1  = (const float*)d_in[5];
    const float* b_hh1  = (const float*)d_in[6];
    const float* W_ih2  = (const float*)d_in[7];
    const float* W_hh2  = (const float*)d_in[8];
    const float* b_ih2  = (const float*)d_in[9];
    const float* b_hh2  = (const float*)d_in[10];
    const float* W_out  = (const float*)d_in[11];
    const float* b_out  = (const float*)d_in[12];
    float* out = (float*)d_out;

    const int threads = 128;
    const int blocks = NB / (threads * 2);  // 2 elements per thread
    navi_kernel<<<blocks, threads>>>(inp, hidden, cell,
                                     W_ih1, W_hh1, b_ih1, b_hh1,
                                     W_ih2, W_hh2, b_ih2, b_hh2,
                                     W_out, b_out, out);
}

// round 3
// speedup vs baseline: 1.1445x; 1.1445x over previous
#include <cuda_runtime.h>
#include <cuda_bf16.h>

// LinearNavigator fused: preproc -> LSTM(2->20) -> LSTM(20->20) -> head -> x[1..5]
// B = 1048576, H = 20. One element per thread; scalar FFMA; float4 broadcast LDS
// for weight rows (80B rows, 16B aligned).
// Output: out[B,5], h_stack[2,B,20], c_stack[2,B,20]

#define NB 1048576
#define HDIM 20

__device__ __forceinline__ float sigmoid_(float x) {
    return __fdividef(1.0f, 1.0f + __expf(-x));
}
__device__ __forceinline__ float tanh_(float x) {
    float e = __expf(2.0f * x);
    return 1.0f - __fdividef(2.0f, e + 1.0f);
}

__global__ __launch_bounds__(128)
void navi_kernel(const float* __restrict__ inp,
                 const float* __restrict__ hidden,
                 const float* __restrict__ cell,
                 const float* __restrict__ W_ih1, const float* __restrict__ W_hh1,
                 const float* __restrict__ b_ih1, const float* __restrict__ b_hh1,
                 const float* __restrict__ W_ih2, const float* __restrict__ W_hh2,
                 const float* __restrict__ b_ih2, const float* __restrict__ b_hh2,
                 const float* __restrict__ W_out, const float* __restrict__ b_out,
                 float* __restrict__ out)
{
    __shared__ __align__(16) float sWih1[80 * 2];
    __shared__ __align__(16) float sWhh1[80 * HDIM];
    __shared__ __align__(16) float sWih2[80 * HDIM];
    __shared__ __align__(16) float sWhh2[80 * HDIM];
    __shared__ __align__(16) float sb1[80];
    __shared__ __align__(16) float sb2[80];
    __shared__ __align__(16) float sWo[HDIM];
    __shared__ float sbo;

    const int t = threadIdx.x;
    for (int i = t; i < 160;  i += 128) sWih1[i] = W_ih1[i];
    for (int i = t; i < 1600; i += 128) sWhh1[i] = W_hh1[i];
    for (int i = t; i < 1600; i += 128) sWih2[i] = W_ih2[i];
    for (int i = t; i < 1600; i += 128) sWhh2[i] = W_hh2[i];
    for (int i = t; i < 80;   i += 128) sb1[i] = b_ih1[i] + b_hh1[i];
    for (int i = t; i < 80;   i += 128) sb2[i] = b_ih2[i] + b_hh2[i];
    for (int i = t; i < HDIM; i += 128) sWo[i] = W_out[i];
    if (t == 0) sbo = b_out[0];
    __syncthreads();

    const size_t b = (size_t)blockIdx.x * 128 + t;

    // ---------------- preproc ----------------
    const float v  = inp[b];
    const float av = fabsf(v);
    const float THR = 4.5399929762484854e-05f;  // exp(-10)
    const float E10 = 22026.465794806718f;      // exp(10)
    float x0, x1;
    if (av >= THR) {
        x0 = __logf(av + 1e-8f) * 0.1f;
        x1 = (v > 0.0f) ? 1.0f : -1.0f;
    } else {
        x0 = -1.0f;
        x1 = E10 * v;
    }

    // ---------------- load layer-1 state (vectorized) ----------------
    float h0[HDIM], c0[HDIM];
    {
        const float4* hp = reinterpret_cast<const float4*>(hidden + b * HDIM);
        const float4* cp = reinterpret_cast<const float4*>(cell   + b * HDIM);
        #pragma unroll
        for (int q = 0; q < 5; q++) {
            float4 hv = hp[q];
            h0[4*q+0] = hv.x; h0[4*q+1] = hv.y; h0[4*q+2] = hv.z; h0[4*q+3] = hv.w;
            float4 cv = cp[q];
            c0[4*q+0] = cv.x; c0[4*q+1] = cv.y; c0[4*q+2] = cv.z; c0[4*q+3] = cv.w;
        }
    }

    // ---------------- LSTM layer 1 ----------------
    float hn1[HDIM];
    #pragma unroll 1
    for (int j = 0; j < HDIM; j++) {
        // input contribution (2 inputs), weights as float4 per pair of rows is
        // awkward; use scalar for the 2-wide part (8 LDS / j).
        float gi = sb1[j]      + x0 * sWih1[2*j]        + x1 * sWih1[2*j + 1];
        float gf = sb1[j + 20] + x0 * sWih1[2*(j+20)]   + x1 * sWih1[2*(j+20) + 1];
        float gg = sb1[j + 40] + x0 * sWih1[2*(j+40)]   + x1 * sWih1[2*(j+40) + 1];
        float go = sb1[j + 60] + x0 * sWih1[2*(j+60)]   + x1 * sWih1[2*(j+60) + 1];
        const float4* wi = reinterpret_cast<const float4*>(&sWhh1[j * HDIM]);
        const float4* wf = reinterpret_cast<const float4*>(&sWhh1[(j + 20) * HDIM]);
        const float4* wg = reinterpret_cast<const float4*>(&sWhh1[(j + 40) * HDIM]);
        const float4* wo = reinterpret_cast<const float4*>(&sWhh1[(j + 60) * HDIM]);
        #pragma unroll
        for (int p = 0; p < 5; p++) {
            const float ha = h0[4*p], hb = h0[4*p+1], hc = h0[4*p+2], hd = h0[4*p+3];
            float4 w;
            w = wi[p]; gi += ha*w.x + hb*w.y + hc*w.z + hd*w.w;
            w = wf[p]; gf += ha*w.x + hb*w.y + hc*w.z + hd*w.w;
            w = wg[p]; gg += ha*w.x + hb*w.y + hc*w.z + hd*w.w;
            w = wo[p]; go += ha*w.x + hb*w.y + hc*w.z + hd*w.w;
        }
        const float cn = sigmoid_(gf) * c0[j] + sigmoid_(gi) * tanh_(gg);
        hn1[j] = sigmoid_(go) * tanh_(cn);
        c0[j] = cn;  // staging for c0_new
    }

    // ---------------- store layer-1 outputs ----------------
    {
        float4* hp = reinterpret_cast<float4*>(out + (size_t)5 * NB + b * HDIM);
        float4* cp = reinterpret_cast<float4*>(out + (size_t)5 * NB + (size_t)2 * NB * HDIM + b * HDIM);
        #pragma unroll
        for (int q = 0; q < 5; q++) {
            hp[q] = make_float4(hn1[4*q], hn1[4*q+1], hn1[4*q+2], hn1[4*q+3]);
            cp[q] = make_float4(c0[4*q],  c0[4*q+1],  c0[4*q+2],  c0[4*q+3]);
        }
    }

    // ---------------- load layer-2 state ----------------
    float h1[HDIM], c1[HDIM];
    {
        const float4* hp = reinterpret_cast<const float4*>(hidden + (size_t)NB * HDIM + b * HDIM);
        const float4* cp = reinterpret_cast<const float4*>(cell   + (size_t)NB * HDIM + b * HDIM);
        #pragma unroll
        for (int q = 0; q < 5; q++) {
            float4 hv = hp[q];
            h1[4*q+0] = hv.x; h1[4*q+1] = hv.y; h1[4*q+2] = hv.z; h1[4*q+3] = hv.w;
            float4 cv = cp[q];
            c1[4*q+0] = cv.x; c1[4*q+1] = cv.y; c1[4*q+2] = cv.z; c1[4*q+3] = cv.w;
        }
    }

    // ---------------- LSTM layer 2 ----------------
    float hn2[HDIM];
    #pragma unroll 1
    for (int j = 0; j < HDIM; j++) {
        float gi = sb2[j];
        float gf = sb2[j + 20];
        float gg = sb2[j + 40];
        float go = sb2[j + 60];
        const float4* xi = reinterpret_cast<const float4*>(&sWih2[j * HDIM]);
        const float4* xf = reinterpret_cast<const float4*>(&sWih2[(j + 20) * HDIM]);
        const float4* xg = reinterpret_cast<const float4*>(&sWih2[(j + 40) * HDIM]);
        const float4* xo = reinterpret_cast<const float4*>(&sWih2[(j + 60) * HDIM]);
        const float4* ri = reinterpret_cast<const float4*>(&sWhh2[j * HDIM]);
        const float4* rf = reinterpret_cast<const float4*>(&sWhh2[(j + 20) * HDIM]);
        const float4* rg = reinterpret_cast<const float4*>(&sWhh2[(j + 40) * HDIM]);
        const float4* ro = reinterpret_cast<const float4*>(&sWhh2[(j + 60) * HDIM]);
        #pragma unroll
        for (int p = 0; p < 5; p++) {
            const float xa = hn1[4*p], xb = hn1[4*p+1], xc = hn1[4*p+2], xd = hn1[4*p+3];
            const float ha = h1[4*p],  hb2 = h1[4*p+1], hc = h1[4*p+2], hd = h1[4*p+3];
            float4 w;
            w = xi[p]; gi += xa*w.x + xb*w.y + xc*w.z + xd*w.w;
            w = ri[p]; gi += ha*w.x + hb2*w.y + hc*w.z + hd*w.w;
            w = xf[p]; gf += xa*w.x + xb*w.y + xc*w.z + xd*w.w;
            w = rf[p]; gf += ha*w.x + hb2*w.y + hc*w.z + hd*w.w;
            w = xg[p]; gg += xa*w.x + xb*w.y + xc*w.z + xd*w.w;
            w = rg[p]; gg += ha*w.x + hb2*w.y + hc*w.z + hd*w.w;
            w = xo[p]; go += xa*w.x + xb*w.y + xc*w.z + xd*w.w;
            w = ro[p]; go += ha*w.x + hb2*w.y + hc*w.z + hd*w.w;
        }
        const float cn = sigmoid_(gf) * c1[j] + sigmoid_(gi) * tanh_(gg);
        hn2[j] = sigmoid_(go) * tanh_(cn);
        c1[j] = cn;
    }

    // ---------------- output head ----------------
    float o = sbo;
    #pragma unroll
    for (int k = 0; k < HDIM; k++) o += hn2[k] * sWo[k];

    // ---------------- stores ----------------
    float* out5 = out + b * 5;
    #pragma unroll
    for (int s = 0; s < 5; s++) out5[s] = o * (float)(s + 1);

    float* hbase = out + (size_t)5 * NB;
    float* cbase = out + (size_t)5 * NB + (size_t)2 * NB * HDIM;
    float4* h1p = reinterpret_cast<float4*>(hbase + (size_t)NB * HDIM + b * HDIM);
    float4* c1p = reinterpret_cast<float4*>(cbase + (size_t)NB * HDIM + b * HDIM);
    #pragma unroll
    for (int q = 0; q < 5; q++) {
        h1p[q] = make_float4(hn2[4*q], hn2[4*q+1], hn2[4*q+2], hn2[4*q+3]);
        c1p[q] = make_float4(c1[4*q],  c1[4*q+1],  c1[4*q+2],  c1[4*q+3]);
    }
}

extern "C" void kernel_launch(void* const* d_in, const int* in_sizes, int n_in,
                              void* d_out, int out_size) {
    const float* inp    = (const float*)d_in[0];
    const float* hidden = (const float*)d_in[1];
    const float* cell   = (const float*)d_in[2];
    const float* W_ih1  = (const float*)d_in[3];
    const float* W_hh1  = (const float*)d_in[4];
    const float* b_ih1  = (const float*)d_in[5];
    const float* b_hh1  = (const float*)d_in[6];
    const float* W_ih2  = (const float*)d_in[7];
    const float* W_hh2  = (const float*)d_in[8];
    const float* b_ih2  = (const float*)d_in[9];
    const float* b_hh2  = (const float*)d_in[10];
    const float* W_out  = (const float*)d_in[11];
    const float* b_out  = (const float*)d_in[12];
    float* out = (float*)d_out;

    const int threads = 128;
    const int blocks = NB / threads;
    navi_kernel<<<blocks, threads>>>(inp, hidden, cell,
                                     W_ih1, W_hh1, b_ih1, b_hh1,
                                     W_ih2, W_hh2, b_ih2, b_hh2,
                                     W_out, b_out, out);
}